// round 5
// baseline (speedup 1.0000x reference)
#include <cuda_runtime.h>
#include <cuda_bf16.h>
#include <math.h>
#include <stdint.h>

// ---------------- problem constants ----------------
#define S_   2048
#define HID_ 2048
#define H_   16
#define NOPE_ 128
#define ROPE_ 64
#define VD_  128
#define QH_  192
#define QL_  1536
#define KVL_ 512
#define CKV_ 576
#define INTER_ 8192
#define HQH_ 3072
#define KVOUT_ 256
#define KFD_ 192

// ---------------- scratch ----------------
#define OFF_H1       0L
#define OFF_QA       4194304L
#define OFF_Q        7340032L
#define OFF_CKV      13631488L
#define OFF_KVLN     14811136L
#define OFF_KV       15859712L
#define OFF_KF       16384000L
#define OFF_KFT      16777216L
#define OFF_ATTNO    17170432L
#define OFF_ATTNPROJ 21364736L
#define OFF_X        25559040L
#define OFF_H2       29753344L
#define OFF_GU       33947648L
#define OFF_ACT      67502080L
#define OFF_MLP      84279296L
#define OFF_SCORES   88473600L
// rounded-weight copies
#define OFF_W_QA     155582464L
#define OFF_W_QB     158728192L
#define OFF_W_KV     163446784L
#define OFF_W_KVI    164626432L   // compact 512x256
#define OFF_W_O      164757504L
#define OFF_W_GU     168951808L
#define OFF_W_DN     202506240L
#define SCRATCH_FLOATS 219283456L

__device__ float g_scratch[SCRATCH_FLOATS];

__device__ __forceinline__ uint32_t f2tf32(float f) {
    uint32_t u;
    asm("cvt.rna.tf32.f32 %0, %1;" : "=r"(u) : "f"(f));
    return u;
}
__device__ __forceinline__ float tf32r(float f) {
    return __uint_as_float(f2tf32(f));
}

// ---------------- reductions ----------------
__device__ __forceinline__ float warp_sum(float v) {
    #pragma unroll
    for (int o = 16; o > 0; o >>= 1) v += __shfl_xor_sync(0xffffffffu, v, o);
    return v;
}
__device__ __forceinline__ float warp_max(float v) {
    #pragma unroll
    for (int o = 16; o > 0; o >>= 1) v = fmaxf(v, __shfl_xor_sync(0xffffffffu, v, o));
    return v;
}
__device__ float block_sum(float v) {
    __shared__ float sh[32];
    int lane = threadIdx.x & 31, wid = threadIdx.x >> 5, nw = (blockDim.x + 31) >> 5;
    v = warp_sum(v);
    __syncthreads();
    if (lane == 0) sh[wid] = v;
    __syncthreads();
    if (wid == 0) {
        float x = (lane < nw) ? sh[lane] : 0.f;
        x = warp_sum(x);
        if (lane == 0) sh[0] = x;
    }
    __syncthreads();
    return sh[0];
}
__device__ float block_max(float v) {
    __shared__ float sh[32];
    int lane = threadIdx.x & 31, wid = threadIdx.x >> 5, nw = (blockDim.x + 31) >> 5;
    v = warp_max(v);
    __syncthreads();
    if (lane == 0) sh[wid] = v;
    __syncthreads();
    if (wid == 0) {
        float x = (lane < nw) ? sh[lane] : -3.4e38f;
        x = warp_max(x);
        if (lane == 0) sh[0] = x;
    }
    __syncthreads();
    return sh[0];
}

// ---------------- weight rounding (copy, cvt.rna to tf32 bits) -------------
__global__ void round_copy_kernel(const float* __restrict__ src, float* __restrict__ dst, long n) {
    long i = ((long)blockIdx.x * blockDim.x + threadIdx.x) * 4;
    if (i + 3 < n) {
        float4 v = *(const float4*)(src + i);
        v.x = tf32r(v.x); v.y = tf32r(v.y); v.z = tf32r(v.z); v.w = tf32r(v.w);
        *(float4*)(dst + i) = v;
    } else {
        for (; i < n; i++) dst[i] = tf32r(src[i]);
    }
}
// compact + round: dst[r][0..cols) = src[r*ldsrc + 0..cols)
__global__ void round_copy_strided_kernel(const float* __restrict__ src, float* __restrict__ dst,
                                          int rows, int cols, int ldsrc) {
    long i = ((long)blockIdx.x * blockDim.x + threadIdx.x) * 4;
    long n = (long)rows * cols;
    if (i + 3 < n) {
        int r = (int)(i / cols), c = (int)(i % cols);
        float4 v = *(const float4*)(src + (long)r * ldsrc + c);
        v.x = tf32r(v.x); v.y = tf32r(v.y); v.z = tf32r(v.z); v.w = tf32r(v.w);
        *(float4*)(dst + i) = v;
    }
}

// ---------------- elementwise / norm kernels ----------------
__global__ void rms_kernel(const float* __restrict__ in, const float* __restrict__ res,
                           const float* __restrict__ w, float* __restrict__ out, int N, int roundOut) {
    int row = blockIdx.x;
    const float* x = in + (long)row * N;
    float sq = 0.f;
    for (int i = threadIdx.x; i < N; i += blockDim.x) { float v = x[i]; sq += v * v; }
    sq = block_sum(sq);
    float scale = rsqrtf(sq / (float)N + 1e-6f);
    float* o = out + (long)row * N;
    const float* r = res ? res + (long)row * N : nullptr;
    for (int i = threadIdx.x; i < N; i += blockDim.x) {
        float v = (r ? r[i] : 0.f) + x[i] * scale * w[i];
        o[i] = roundOut ? tf32r(v) : v;
    }
}

__global__ void ln_kernel(const float* __restrict__ in, const float* __restrict__ s,
                          const float* __restrict__ b, float* __restrict__ out,
                          int N, int ldin, int ldout) {
    int row = blockIdx.x;
    const float* x = in + (long)row * ldin;
    float sum = 0.f, sq = 0.f;
    for (int i = threadIdx.x; i < N; i += blockDim.x) { float v = x[i]; sum += v; sq += v * v; }
    sum = block_sum(sum);
    sq = block_sum(sq);
    float m = sum / (float)N;
    float var = sq / (float)N - m * m;
    float r = rsqrtf(var + 1e-6f);
    float* o = out + (long)row * ldout;
    for (int i = threadIdx.x; i < N; i += blockDim.x)
        o[i] = tf32r((x[i] - m) * r * s[i] + b[i]);   // GEMM-input: pre-round
}

__global__ void rope_q_kernel(float* __restrict__ q, const int* __restrict__ pos) {
    int srow = blockIdx.x;
    int t = threadIdx.x;
    int h = t >> 5, j = t & 31;
    float p = (float)pos[srow];
    float invf = expf(-((float)(2 * j)) / 64.f * 9.210340371976184f);
    float sn, c;
    sincosf(p * invf, &sn, &c);
    long base = (long)srow * HQH_ + h * QH_ + NOPE_;
    float x1 = q[base + j], x2 = q[base + 32 + j];
    q[base + j]      = tf32r(x1 * c - x2 * sn);
    q[base + 32 + j] = tf32r(x2 * c + x1 * sn);
}

__global__ void rope_k_kernel(const float* __restrict__ ckv, const float* __restrict__ kv,
                              const int* __restrict__ pos, float* __restrict__ kf) {
    int srow = blockIdx.x;
    int t = threadIdx.x;
    if (t < 128) {
        kf[(long)srow * KFD_ + t] = kv[(long)srow * KVOUT_ + t];   // already rounded
    } else if (t < 160) {
        int j = t - 128;
        float p = (float)pos[srow];
        float invf = expf(-((float)(2 * j)) / 64.f * 9.210340371976184f);
        float sn, c;
        sincosf(p * invf, &sn, &c);
        const float* kp = ckv + (long)srow * CKV_ + KVL_;
        float x1 = kp[j], x2 = kp[32 + j];
        kf[(long)srow * KFD_ + 128 + j] = tf32r(x1 * c - x2 * sn);
        kf[(long)srow * KFD_ + 160 + j] = tf32r(x2 * c + x1 * sn);
    }
}

__global__ void transpose_kf_kernel(const float* __restrict__ kf, float* __restrict__ kfT) {
    int idx = blockIdx.x * blockDim.x + threadIdx.x;
    if (idx < S_ * KFD_) {
        int srow = idx / KFD_, d = idx % KFD_;
        kfT[(long)d * S_ + srow] = kf[idx];
    }
}

__global__ void softmax_kernel(float* __restrict__ scores) {
    int q = blockIdx.x, h = blockIdx.y;
    float* row = scores + ((long)h * S_ + q) * S_;
    float mx = -3.4e38f;
    for (int k = threadIdx.x; k <= q; k += blockDim.x)
        mx = fmaxf(mx, row[k]);
    mx = block_max(mx);
    float sum = 0.f;
    for (int k = threadIdx.x; k < S_; k += blockDim.x) {
        float e = (k <= q) ? expf(row[k] - mx) : 0.f;
        row[k] = e;
        sum += e;
    }
    sum = block_sum(sum);
    float inv = 1.f / sum;
    for (int k = threadIdx.x; k <= q; k += blockDim.x) row[k] = tf32r(row[k] * inv);
}

__global__ void silu_mul_kernel(const float* __restrict__ gu, float* __restrict__ act) {
    long idx = (long)blockIdx.x * blockDim.x + threadIdx.x;
    int srow = (int)(idx >> 13);
    int i = (int)(idx & 8191);
    float g = gu[(long)srow * (2 * INTER_) + i];
    float u = gu[(long)srow * (2 * INTER_) + INTER_ + i];
    act[idx] = tf32r(u * g / (1.f + expf(-g)));
}

// ---------------- TF32 tensor-core GEMM with cp.async pipeline ----------------
// All operands PRE-ROUNDED to tf32 (stored as fp32 bits) -> no cvt in hot loop.
__device__ __forceinline__ void cp_async16(uint32_t dst, const void* src, int szbytes) {
    asm volatile("cp.async.cg.shared.global [%0], [%1], 16, %2;\n"
                 :: "r"(dst), "l"(src), "r"(szbytes));
}

#define AS_STRIDE 36
#define BS_STRIDE 132
#define A_STAGE (128 * AS_STRIDE)
#define B_STAGE (32 * BS_STRIDE)
#define GEMM_SMEM_BYTES ((2 * A_STAGE + 2 * B_STAGE) * 4)

__global__ __launch_bounds__(256, 2) void tf32gemm_kernel(
    const float* __restrict__ A, const float* __restrict__ B, float* __restrict__ C,
    int M, int N, int K, int lda, int ldb, int ldc,
    long strideA, long strideB, long strideC, float alpha, int roundC)
{
    A += (long)blockIdx.z * strideA;
    B += (long)blockIdx.z * strideB;
    C += (long)blockIdx.z * strideC;
    const int bm = blockIdx.y * 128;
    const int bn = blockIdx.x * 128;

    extern __shared__ float smemf[];
    float* AsF = smemf;
    float* BsF = smemf + 2 * A_STAGE;
    uint32_t as_base = (uint32_t)__cvta_generic_to_shared(AsF);
    uint32_t bs_base = (uint32_t)__cvta_generic_to_shared(BsF);

    const int t = threadIdx.x;
    const int warp = t >> 5;
    const int lane = t & 31;
    const int g  = lane >> 2;
    const int tg = lane & 3;
    const int wm = (warp & 1) * 64;
    const int wn = (warp >> 1) * 32;

    const int a_row0 = t >> 3;
    const int a_c4   = (t & 7) * 4;
    const int b_row0 = t >> 5;
    const int b_c4   = (t & 31) * 4;

    float acc[4][4][4];
    #pragma unroll
    for (int i = 0; i < 4; i++)
        #pragma unroll
        for (int j = 0; j < 4; j++)
            #pragma unroll
            for (int r = 0; r < 4; r++) acc[i][j][r] = 0.f;

    const int ntiles = K >> 5;

    auto stage = [&](int kt, int s) {
        int k0 = kt << 5;
        uint32_t aoff = as_base + (uint32_t)(s * A_STAGE) * 4u;
        #pragma unroll
        for (int it = 0; it < 4; it++) {
            int row = a_row0 + 32 * it;
            cp_async16(aoff + (uint32_t)(row * AS_STRIDE + a_c4) * 4u,
                       A + (long)(bm + row) * lda + k0 + a_c4, 16);
        }
        uint32_t boff = bs_base + (uint32_t)(s * B_STAGE) * 4u;
        #pragma unroll
        for (int it = 0; it < 4; it++) {
            int row = b_row0 + 8 * it;
            int col = bn + b_c4;
            int sz = (col < N) ? 16 : 0;
            cp_async16(boff + (uint32_t)(row * BS_STRIDE + b_c4) * 4u,
                       B + (long)(k0 + row) * ldb + col, sz);
        }
    };

    stage(0, 0);
    asm volatile("cp.async.commit_group;\n");

    for (int kt = 0; kt < ntiles; kt++) {
        if (kt + 1 < ntiles) stage(kt + 1, (kt + 1) & 1);
        asm volatile("cp.async.commit_group;\n");
        asm volatile("cp.async.wait_group 1;\n");
        __syncthreads();

        const uint32_t* As = (const uint32_t*)(AsF + (kt & 1) * A_STAGE);
        const uint32_t* Bs = (const uint32_t*)(BsF + (kt & 1) * B_STAGE);

        #pragma unroll
        for (int kk = 0; kk < 32; kk += 8) {
            uint32_t af[4][4];
            #pragma unroll
            for (int i = 0; i < 4; i++) {
                int r0 = wm + 16 * i + g;
                af[i][0] = As[(r0)     * AS_STRIDE + kk + tg];
                af[i][1] = As[(r0 + 8) * AS_STRIDE + kk + tg];
                af[i][2] = As[(r0)     * AS_STRIDE + kk + tg + 4];
                af[i][3] = As[(r0 + 8) * AS_STRIDE + kk + tg + 4];
            }
            uint32_t bf[4][2];
            #pragma unroll
            for (int j = 0; j < 4; j++) {
                int c0 = wn + 8 * j + g;
                bf[j][0] = Bs[(kk + tg)     * BS_STRIDE + c0];
                bf[j][1] = Bs[(kk + tg + 4) * BS_STRIDE + c0];
            }
            #pragma unroll
            for (int i = 0; i < 4; i++)
                #pragma unroll
                for (int j = 0; j < 4; j++) {
                    asm volatile(
                        "mma.sync.aligned.m16n8k8.row.col.f32.tf32.tf32.f32 "
                        "{%0,%1,%2,%3}, {%4,%5,%6,%7}, {%8,%9}, {%0,%1,%2,%3};\n"
                        : "+f"(acc[i][j][0]), "+f"(acc[i][j][1]),
                          "+f"(acc[i][j][2]), "+f"(acc[i][j][3])
                        : "r"(af[i][0]), "r"(af[i][1]), "r"(af[i][2]), "r"(af[i][3]),
                          "r"(bf[j][0]), "r"(bf[j][1]));
                }
        }
        __syncthreads();
    }

    #pragma unroll
    for (int i = 0; i < 4; i++) {
        #pragma unroll
        for (int j = 0; j < 4; j++) {
            int r0 = bm + wm + 16 * i + g;
            int c0 = bn + wn + 8 * j + 2 * tg;
            if (c0 < N) {
                float v0 = acc[i][j][0] * alpha, v1 = acc[i][j][1] * alpha;
                float v2 = acc[i][j][2] * alpha, v3 = acc[i][j][3] * alpha;
                if (roundC) { v0 = tf32r(v0); v1 = tf32r(v1); v2 = tf32r(v2); v3 = tf32r(v3); }
                *(float2*)(C + (long)r0 * ldc + c0)       = make_float2(v0, v1);
                *(float2*)(C + (long)(r0 + 8) * ldc + c0) = make_float2(v2, v3);
            }
        }
    }
}

static inline void launch_gemm(const float* A, const float* B, float* C,
                               int M, int N, int K, int lda, int ldb, int ldc,
                               long sA, long sB, long sC, float alpha, int batch, int roundC) {
    static bool attr_set = false;
    if (!attr_set) {
        cudaFuncSetAttribute(tf32gemm_kernel,
                             cudaFuncAttributeMaxDynamicSharedMemorySize, GEMM_SMEM_BYTES);
        attr_set = true;
    }
    dim3 grid((N + 127) / 128, M / 128, batch);
    tf32gemm_kernel<<<grid, 256, GEMM_SMEM_BYTES>>>(A, B, C, M, N, K, lda, ldb, ldc,
                                                    sA, sB, sC, alpha, roundC);
}

// ---------------- entry ----------------
extern "C" void kernel_launch(void* const* d_in, const int* in_sizes, int n_in,
                              void* d_out, int out_size) {
    const float* hidden      = (const float*)d_in[0];
    // d_in[1] attention_mask: all-ones; unused (pure causal).
    const int*   pos         = (const int*)d_in[2];
    const float* w_in        = (const float*)d_in[3];
    const float* w_post_attn = (const float*)d_in[4];
    const float* w_pre_ff    = (const float*)d_in[5];
    const float* w_post_ff   = (const float*)d_in[6];
    const float* qa_w        = (const float*)d_in[7];
    const float* qa_ln_s     = (const float*)d_in[8];
    const float* qa_ln_b     = (const float*)d_in[9];
    const float* qb_w        = (const float*)d_in[10];
    const float* kv_mqa_w    = (const float*)d_in[11];
    const float* kv_ln_s     = (const float*)d_in[12];
    const float* kv_ln_b     = (const float*)d_in[13];
    const float* kvi_w       = (const float*)d_in[14];
    const float* o_w         = (const float*)d_in[15];
    const float* gate_up_w   = (const float*)d_in[16];
    const float* down_w      = (const float*)d_in[17];
    float* out = (float*)d_out;

    float* sc = nullptr;
    cudaGetSymbolAddress((void**)&sc, g_scratch);
    float* h1       = sc + OFF_H1;
    float* qa       = sc + OFF_QA;
    float* q        = sc + OFF_Q;
    float* ckv      = sc + OFF_CKV;
    float* kvln     = sc + OFF_KVLN;
    float* kv       = sc + OFF_KV;
    float* kf       = sc + OFF_KF;
    float* kfT      = sc + OFF_KFT;
    float* attno    = sc + OFF_ATTNO;
    float* attnproj = sc + OFF_ATTNPROJ;
    float* x        = sc + OFF_X;
    float* h2       = sc + OFF_H2;
    float* gu       = sc + OFF_GU;
    float* act      = sc + OFF_ACT;
    float* mlp      = sc + OFF_MLP;
    float* scores   = sc + OFF_SCORES;
    float* w_qa_r   = sc + OFF_W_QA;
    float* w_qb_r   = sc + OFF_W_QB;
    float* w_kv_r   = sc + OFF_W_KV;
    float* w_kvi_r  = sc + OFF_W_KVI;
    float* w_o_r    = sc + OFF_W_O;
    float* w_gu_r   = sc + OFF_W_GU;
    float* w_dn_r   = sc + OFF_W_DN;

    // ---- round weights to tf32 bits (idempotent, graph-capturable) ----
    auto rc = [&](const float* s, float* d, long n) {
        round_copy_kernel<<<(int)((n / 4 + 255) / 256), 256>>>(s, d, n);
    };
    rc(qa_w,      w_qa_r, (long)HID_ * QL_);
    rc(qb_w,      w_qb_r, (long)QL_ * HQH_);
    rc(kv_mqa_w,  w_kv_r, (long)HID_ * CKV_);
    round_copy_strided_kernel<<<(KVL_ * KVOUT_ / 4 + 255) / 256, 256>>>(
        kvi_w, w_kvi_r, KVL_, KVOUT_, H_ * (NOPE_ + VD_));
    rc(o_w,       w_o_r,  (long)HID_ * HID_);
    rc(gate_up_w, w_gu_r, (long)HID_ * 2 * INTER_);
    rc(down_w,    w_dn_r, (long)INTER_ * HID_);

    // 1. h1 = rms(hidden)*w_in  (GEMM input -> rounded)
    rms_kernel<<<S_, 256>>>(hidden, nullptr, w_in, h1, HID_, 1);

    launch_gemm(h1, w_qa_r, qa, S_, QL_, HID_, HID_, QL_, QL_, 0, 0, 0, 1.f, 1, 0);
    ln_kernel<<<S_, 256>>>(qa, qa_ln_s, qa_ln_b, qa, QL_, QL_, QL_);

    launch_gemm(qa, w_qb_r, q, S_, HQH_, QL_, QL_, HQH_, HQH_, 0, 0, 0, 1.f, 1, 1);

    launch_gemm(h1, w_kv_r, ckv, S_, CKV_, HID_, HID_, CKV_, CKV_, 0, 0, 0, 1.f, 1, 0);
    ln_kernel<<<S_, 256>>>(ckv, kv_ln_s, kv_ln_b, kvln, KVL_, CKV_, KVL_);

    launch_gemm(kvln, w_kvi_r, kv, S_, KVOUT_, KVL_, KVL_, KVOUT_, KVOUT_, 0, 0, 0, 1.f, 1, 1);

    rope_q_kernel<<<S_, 512>>>(q, pos);
    rope_k_kernel<<<S_, 256>>>(ckv, kv, pos, kf);
    transpose_kf_kernel<<<(S_ * KFD_ + 255) / 256, 256>>>(kf, kfT);

    const float scale = 0.07216878364870323f;   // 192^-0.5
    launch_gemm(q, kfT, scores, S_, S_, KFD_, HQH_, S_, S_,
                (long)QH_, 0L, (long)S_ * S_, scale, H_, 0);

    softmax_kernel<<<dim3(S_, H_), 256>>>(scores);

    launch_gemm(scores, kv + NOPE_, attno, S_, VD_, S_, S_, KVOUT_, HID_,
                (long)S_ * S_, 0L, (long)VD_, 1.f, H_, 1);

    launch_gemm(attno, w_o_r, attnproj, S_, HID_, HID_, HID_, HID_, HID_, 0, 0, 0, 1.f, 1, 0);

    rms_kernel<<<S_, 256>>>(attnproj, hidden, w_post_attn, x, HID_, 0);
    rms_kernel<<<S_, 256>>>(x, nullptr, w_pre_ff, h2, HID_, 1);

    launch_gemm(h2, w_gu_r, gu, S_, 2 * INTER_, HID_, HID_, 2 * INTER_, 2 * INTER_, 0, 0, 0, 1.f, 1, 0);
    silu_mul_kernel<<<(S_ * INTER_) / 256, 256>>>(gu, act);

    launch_gemm(act, w_dn_r, mlp, S_, HID_, INTER_, INTER_, HID_, HID_, 0, 0, 0, 1.f, 1, 0);

    rms_kernel<<<S_, 256>>>(mlp, x, w_post_ff, out, HID_, 0);
}

// round 7
// speedup vs baseline: 1.1046x; 1.1046x over previous
#include <cuda_runtime.h>
#include <cuda_bf16.h>
#include <math.h>
#include <stdint.h>

// ---------------- problem constants ----------------
#define S_   2048
#define HID_ 2048
#define H_   16
#define NOPE_ 128
#define ROPE_ 64
#define VD_  128
#define QH_  192
#define QL_  1536
#define KVL_ 512
#define CKV_ 576
#define INTER_ 8192
#define HQH_ 3072
#define KVOUT_ 256
#define KFD_ 192

// ---------------- scratch ----------------
#define OFF_H1       0L
#define OFF_QA       4194304L
#define OFF_Q        7340032L
#define OFF_CKV      13631488L
#define OFF_KVLN     14811136L
#define OFF_KV       15859712L
#define OFF_KF       16384000L
#define OFF_KFT      16777216L
#define OFF_ATTNO    17170432L
#define OFF_ATTNPROJ 21364736L
#define OFF_X        25559040L
#define OFF_H2       29753344L
#define OFF_GU       33947648L
#define OFF_ACT      67502080L
#define OFF_MLP      84279296L
#define OFF_SCORES   88473600L
#define SCRATCH_FLOATS 155582464L

__device__ float g_scratch[SCRATCH_FLOATS];

__device__ __forceinline__ uint32_t f2tf32(float f) {
    uint32_t u;
    asm("cvt.rna.tf32.f32 %0, %1;" : "=r"(u) : "f"(f));
    return u;
}

// ---------------- reductions ----------------
__device__ __forceinline__ float warp_sum(float v) {
    #pragma unroll
    for (int o = 16; o > 0; o >>= 1) v += __shfl_xor_sync(0xffffffffu, v, o);
    return v;
}
__device__ __forceinline__ float warp_max(float v) {
    #pragma unroll
    for (int o = 16; o > 0; o >>= 1) v = fmaxf(v, __shfl_xor_sync(0xffffffffu, v, o));
    return v;
}
__device__ float block_sum(float v) {
    __shared__ float sh[32];
    int lane = threadIdx.x & 31, wid = threadIdx.x >> 5, nw = (blockDim.x + 31) >> 5;
    v = warp_sum(v);
    __syncthreads();
    if (lane == 0) sh[wid] = v;
    __syncthreads();
    if (wid == 0) {
        float x = (lane < nw) ? sh[lane] : 0.f;
        x = warp_sum(x);
        if (lane == 0) sh[0] = x;
    }
    __syncthreads();
    return sh[0];
}
__device__ float block_max(float v) {
    __shared__ float sh[32];
    int lane = threadIdx.x & 31, wid = threadIdx.x >> 5, nw = (blockDim.x + 31) >> 5;
    v = warp_max(v);
    __syncthreads();
    if (lane == 0) sh[wid] = v;
    __syncthreads();
    if (wid == 0) {
        float x = (lane < nw) ? sh[lane] : -3.4e38f;
        x = warp_max(x);
        if (lane == 0) sh[0] = x;
    }
    __syncthreads();
    return sh[0];
}

// ---------------- elementwise / norm kernels ----------------
__global__ void rms_kernel(const float* __restrict__ in, const float* __restrict__ res,
                           const float* __restrict__ w, float* __restrict__ out, int N) {
    int row = blockIdx.x;
    const float* x = in + (long)row * N;
    float sq = 0.f;
    for (int i = threadIdx.x; i < N; i += blockDim.x) { float v = x[i]; sq += v * v; }
    sq = block_sum(sq);
    float scale = rsqrtf(sq / (float)N + 1e-6f);
    float* o = out + (long)row * N;
    const float* r = res ? res + (long)row * N : nullptr;
    for (int i = threadIdx.x; i < N; i += blockDim.x)
        o[i] = (r ? r[i] : 0.f) + x[i] * scale * w[i];
}

__global__ void ln_kernel(const float* __restrict__ in, const float* __restrict__ s,
                          const float* __restrict__ b, float* __restrict__ out,
                          int N, int ldin, int ldout) {
    int row = blockIdx.x;
    const float* x = in + (long)row * ldin;
    float sum = 0.f, sq = 0.f;
    for (int i = threadIdx.x; i < N; i += blockDim.x) { float v = x[i]; sum += v; sq += v * v; }
    sum = block_sum(sum);
    sq = block_sum(sq);
    float m = sum / (float)N;
    float var = sq / (float)N - m * m;
    float r = rsqrtf(var + 1e-6f);
    float* o = out + (long)row * ldout;
    for (int i = threadIdx.x; i < N; i += blockDim.x)
        o[i] = (x[i] - m) * r * s[i] + b[i];
}

__global__ void rope_q_kernel(float* __restrict__ q, const int* __restrict__ pos) {
    int srow = blockIdx.x;
    int t = threadIdx.x;
    int h = t >> 5, j = t & 31;
    float p = (float)pos[srow];
    float invf = expf(-((float)(2 * j)) / 64.f * 9.210340371976184f);
    float sn, c;
    sincosf(p * invf, &sn, &c);
    long base = (long)srow * HQH_ + h * QH_ + NOPE_;
    float x1 = q[base + j], x2 = q[base + 32 + j];
    q[base + j]      = x1 * c - x2 * sn;
    q[base + 32 + j] = x2 * c + x1 * sn;
}

__global__ void rope_k_kernel(const float* __restrict__ ckv, const float* __restrict__ kv,
                              const int* __restrict__ pos, float* __restrict__ kf) {
    int srow = blockIdx.x;
    int t = threadIdx.x;
    if (t < 128) {
        kf[(long)srow * KFD_ + t] = kv[(long)srow * KVOUT_ + t];
    } else if (t < 160) {
        int j = t - 128;
        float p = (float)pos[srow];
        float invf = expf(-((float)(2 * j)) / 64.f * 9.210340371976184f);
        float sn, c;
        sincosf(p * invf, &sn, &c);
        const float* kp = ckv + (long)srow * CKV_ + KVL_;
        float x1 = kp[j], x2 = kp[32 + j];
        kf[(long)srow * KFD_ + 128 + j] = x1 * c - x2 * sn;
        kf[(long)srow * KFD_ + 160 + j] = x2 * c + x1 * sn;
    }
}

__global__ void transpose_kf_kernel(const float* __restrict__ kf, float* __restrict__ kfT) {
    int idx = blockIdx.x * blockDim.x + threadIdx.x;
    if (idx < S_ * KFD_) {
        int srow = idx / KFD_, d = idx % KFD_;
        kfT[(long)d * S_ + srow] = kf[idx];
    }
}

__global__ void softmax_kernel(float* __restrict__ scores) {
    int q = blockIdx.x, h = blockIdx.y;
    float* row = scores + ((long)h * S_ + q) * S_;
    float mx = -3.4e38f;
    for (int k = threadIdx.x; k <= q; k += blockDim.x)
        mx = fmaxf(mx, row[k]);
    mx = block_max(mx);
    float sum = 0.f;
    for (int k = threadIdx.x; k < S_; k += blockDim.x) {
        float e = (k <= q) ? expf(row[k] - mx) : 0.f;
        row[k] = e;
        sum += e;
    }
    sum = block_sum(sum);
    float inv = 1.f / sum;
    for (int k = threadIdx.x; k <= q; k += blockDim.x) row[k] *= inv;
}

__global__ void silu_mul_kernel(const float* __restrict__ gu, float* __restrict__ act) {
    long idx = (long)blockIdx.x * blockDim.x + threadIdx.x;
    int srow = (int)(idx >> 13);
    int i = (int)(idx & 8191);
    float g = gu[(long)srow * (2 * INTER_) + i];
    float u = gu[(long)srow * (2 * INTER_) + INTER_ + i];
    act[idx] = u * g / (1.f + expf(-g));
}

// ---------------- TF32 tensor-core GEMM (4 warps, 64x64 warp tiles) --------
// C = alpha * A @ B.  A[M,K] row-major, B[K,N] row-major.
// CTA 128x128x32, 128 threads, 3-stage cp.async, conflict-free smem strides.
// mode: 0 normal, 1 causal tile-skip (scores), 2 K-cut at diagonal (PV).
__device__ __forceinline__ void cp_async16(uint32_t dst, const void* src, int szbytes) {
    asm volatile("cp.async.cg.shared.global [%0], [%1], 16, %2;\n"
                 :: "r"(dst), "l"(src), "r"(szbytes));
}

#define AS_STRIDE 36     // 36 mod 32 = 4  -> A frag banks 4g+tg all distinct
#define BS_STRIDE 136    // 136 mod 32 = 8 -> B frag banks 8tg+g all distinct
#define A_STAGE (128 * AS_STRIDE)
#define B_STAGE (32 * BS_STRIDE)
#define NSTAGE 3
#define GEMM_SMEM_BYTES (NSTAGE * (A_STAGE + B_STAGE) * 4)

__global__ __launch_bounds__(128) void tf32gemm_kernel(
    const float* __restrict__ A, const float* __restrict__ B, float* __restrict__ C,
    int M, int N, int K, int lda, int ldb, int ldc,
    long strideA, long strideB, long strideC, float alpha, int mode)
{
    const int bm = blockIdx.y * 128;
    const int bn = blockIdx.x * 128;
    if (mode == 1 && bn >= bm + 128) return;          // causal: tile fully masked

    A += (long)blockIdx.z * strideA;
    B += (long)blockIdx.z * strideB;
    C += (long)blockIdx.z * strideC;

    int ntiles = K >> 5;
    if (mode == 2) { int ke = (bm + 159) >> 5; if (ke < ntiles) ntiles = ke; }

    extern __shared__ float smemf[];
    float* AsF = smemf;                       // [NSTAGE][128][36]
    float* BsF = smemf + NSTAGE * A_STAGE;    // [NSTAGE][32][136]
    uint32_t as_base = (uint32_t)__cvta_generic_to_shared(AsF);
    uint32_t bs_base = (uint32_t)__cvta_generic_to_shared(BsF);

    const int t = threadIdx.x;
    const int warp = t >> 5;
    const int lane = t & 31;
    const int g  = lane >> 2;
    const int tg = lane & 3;
    const int wm = (warp & 1) * 64;
    const int wn = (warp >> 1) * 64;

    // staging coords: 8 float4 chunks each for A and B per K-tile
    const int a_row0 = t >> 3;            // + 16*it
    const int a_c4   = (t & 7) * 4;
    const int b_row0 = t >> 5;            // + 4*it
    const int b_c4   = (t & 31) * 4;

    float acc[4][8][4];
    #pragma unroll
    for (int i = 0; i < 4; i++)
        #pragma unroll
        for (int j = 0; j < 8; j++)
            #pragma unroll
            for (int r = 0; r < 4; r++) acc[i][j][r] = 0.f;

    auto stage = [&](int kt) {
        int s = kt % NSTAGE;
        int k0 = kt << 5;
        uint32_t aoff = as_base + (uint32_t)(s * A_STAGE) * 4u;
        #pragma unroll
        for (int it = 0; it < 8; it++) {
            int row = a_row0 + 16 * it;
            cp_async16(aoff + (uint32_t)(row * AS_STRIDE + a_c4) * 4u,
                       A + (long)(bm + row) * lda + k0 + a_c4, 16);
        }
        uint32_t boff = bs_base + (uint32_t)(s * B_STAGE) * 4u;
        #pragma unroll
        for (int it = 0; it < 8; it++) {
            int row = b_row0 + 4 * it;
            int col = bn + b_c4;
            int sz = (col < N) ? 16 : 0;
            cp_async16(boff + (uint32_t)(row * BS_STRIDE + b_c4) * 4u,
                       B + (long)(k0 + row) * ldb + col, sz);
        }
    };

    // prologue: 2 tiles in flight (ntiles >= 4 always in this layer)
    stage(0);
    asm volatile("cp.async.commit_group;\n");
    stage(1);
    asm volatile("cp.async.commit_group;\n");

    for (int kt = 0; kt < ntiles; kt++) {
        asm volatile("cp.async.wait_group 1;\n");
        __syncthreads();

        const uint32_t* As = (const uint32_t*)(AsF + (kt % NSTAGE) * A_STAGE);
        const uint32_t* Bs = (const uint32_t*)(BsF + (kt % NSTAGE) * B_STAGE);

        #pragma unroll
        for (int kk = 0; kk < 32; kk += 8) {
            uint32_t af[4][4];
            #pragma unroll
            for (int i = 0; i < 4; i++) {
                int r0 = wm + 16 * i + g;
                af[i][0] = f2tf32(__uint_as_float(As[(r0)     * AS_STRIDE + kk + tg]));
                af[i][1] = f2tf32(__uint_as_float(As[(r0 + 8) * AS_STRIDE + kk + tg]));
                af[i][2] = f2tf32(__uint_as_float(As[(r0)     * AS_STRIDE + kk + tg + 4]));
                af[i][3] = f2tf32(__uint_as_float(As[(r0 + 8) * AS_STRIDE + kk + tg + 4]));
            }
            uint32_t bf[8][2];
            #pragma unroll
            for (int j = 0; j < 8; j++) {
                int c0 = wn + 8 * j + g;
                bf[j][0] = f2tf32(__uint_as_float(Bs[(kk + tg)     * BS_STRIDE + c0]));
                bf[j][1] = f2tf32(__uint_as_float(Bs[(kk + tg + 4) * BS_STRIDE + c0]));
            }
            #pragma unroll
            for (int i = 0; i < 4; i++)
                #pragma unroll
                for (int j = 0; j < 8; j++) {
                    asm volatile(
                        "mma.sync.aligned.m16n8k8.row.col.f32.tf32.tf32.f32 "
                        "{%0,%1,%2,%3}, {%4,%5,%6,%7}, {%8,%9}, {%0,%1,%2,%3};\n"
                        : "+f"(acc[i][j][0]), "+f"(acc[i][j][1]),
                          "+f"(acc[i][j][2]), "+f"(acc[i][j][3])
                        : "r"(af[i][0]), "r"(af[i][1]), "r"(af[i][2]), "r"(af[i][3]),
                          "r"(bf[j][0]), "r"(bf[j][1]));
                }
        }
        __syncthreads();
        if (kt + 2 < ntiles) stage(kt + 2);
        asm volatile("cp.async.commit_group;\n");
    }

    #pragma unroll
    for (int i = 0; i < 4; i++) {
        #pragma unroll
        for (int j = 0; j < 8; j++) {
            int r0 = bm + wm + 16 * i + g;
            int c0 = bn + wn + 8 * j + 2 * tg;
            if (c0 < N) {
                float2 v0 = make_float2(acc[i][j][0] * alpha, acc[i][j][1] * alpha);
                float2 v1 = make_float2(acc[i][j][2] * alpha, acc[i][j][3] * alpha);
                *(float2*)(C + (long)r0 * ldc + c0)       = v0;
                *(float2*)(C + (long)(r0 + 8) * ldc + c0) = v1;
            }
        }
    }
}

static inline void launch_gemm(const float* A, const float* B, float* C,
                               int M, int N, int K, int lda, int ldb, int ldc,
                               long sA, long sB, long sC, float alpha, int batch, int mode) {
    static bool attr_set = false;
    if (!attr_set) {
        cudaFuncSetAttribute(tf32gemm_kernel,
                             cudaFuncAttributeMaxDynamicSharedMemorySize, GEMM_SMEM_BYTES);
        attr_set = true;
    }
    dim3 grid((N + 127) / 128, M / 128, batch);
    tf32gemm_kernel<<<grid, 128, GEMM_SMEM_BYTES>>>(A, B, C, M, N, K, lda, ldb, ldc,
                                                    sA, sB, sC, alpha, mode);
}

// ---------------- entry ----------------
extern "C" void kernel_launch(void* const* d_in, const int* in_sizes, int n_in,
                              void* d_out, int out_size) {
    const float* hidden      = (const float*)d_in[0];
    // d_in[1] attention_mask: all-ones; unused (pure causal).
    const int*   pos         = (const int*)d_in[2];
    const float* w_in        = (const float*)d_in[3];
    const float* w_post_attn = (const float*)d_in[4];
    const float* w_pre_ff    = (const float*)d_in[5];
    const float* w_post_ff   = (const float*)d_in[6];
    const float* qa_w        = (const float*)d_in[7];
    const float* qa_ln_s     = (const float*)d_in[8];
    const float* qa_ln_b     = (const float*)d_in[9];
    const float* qb_w        = (const float*)d_in[10];
    const float* kv_mqa_w    = (const float*)d_in[11];
    const float* kv_ln_s     = (const float*)d_in[12];
    const float* kv_ln_b     = (const float*)d_in[13];
    const float* kvi_w       = (const float*)d_in[14];
    const float* o_w         = (const float*)d_in[15];
    const float* gate_up_w   = (const float*)d_in[16];
    const float* down_w      = (const float*)d_in[17];
    float* out = (float*)d_out;

    float* sc = nullptr;
    cudaGetSymbolAddress((void**)&sc, g_scratch);
    float* h1       = sc + OFF_H1;
    float* qa       = sc + OFF_QA;
    float* q        = sc + OFF_Q;
    float* ckv      = sc + OFF_CKV;
    float* kvln     = sc + OFF_KVLN;
    float* kv       = sc + OFF_KV;
    float* kf       = sc + OFF_KF;
    float* kfT      = sc + OFF_KFT;
    float* attno    = sc + OFF_ATTNO;
    float* attnproj = sc + OFF_ATTNPROJ;
    float* x        = sc + OFF_X;
    float* h2       = sc + OFF_H2;
    float* gu       = sc + OFF_GU;
    float* act      = sc + OFF_ACT;
    float* mlp      = sc + OFF_MLP;
    float* scores   = sc + OFF_SCORES;

    rms_kernel<<<S_, 256>>>(hidden, nullptr, w_in, h1, HID_);

    launch_gemm(h1, qa_w, qa, S_, QL_, HID_, HID_, QL_, QL_, 0, 0, 0, 1.f, 1, 0);
    ln_kernel<<<S_, 256>>>(qa, qa_ln_s, qa_ln_b, qa, QL_, QL_, QL_);

    launch_gemm(qa, qb_w, q, S_, HQH_, QL_, QL_, HQH_, HQH_, 0, 0, 0, 1.f, 1, 0);

    launch_gemm(h1, kv_mqa_w, ckv, S_, CKV_, HID_, HID_, CKV_, CKV_, 0, 0, 0, 1.f, 1, 0);
    ln_kernel<<<S_, 256>>>(ckv, kv_ln_s, kv_ln_b, kvln, KVL_, CKV_, KVL_);

    launch_gemm(kvln, kvi_w, kv, S_, KVOUT_, KVL_, KVL_, H_ * (NOPE_ + VD_), KVOUT_, 0, 0, 0, 1.f, 1, 0);

    rope_q_kernel<<<S_, 512>>>(q, pos);
    rope_k_kernel<<<S_, 256>>>(ckv, kv, pos, kf);
    transpose_kf_kernel<<<(S_ * KFD_ + 255) / 256, 256>>>(kf, kfT);

    const float scale = 0.07216878364870323f;   // 192^-0.5
    launch_gemm(q, kfT, scores, S_, S_, KFD_, HQH_, S_, S_,
                (long)QH_, 0L, (long)S_ * S_, scale, H_, 1);

    softmax_kernel<<<dim3(S_, H_), 256>>>(scores);

    launch_gemm(scores, kv + NOPE_, attno, S_, VD_, S_, S_, KVOUT_, HID_,
                (long)S_ * S_, 0L, (long)VD_, 1.f, H_, 2);

    launch_gemm(attno, o_w, attnproj, S_, HID_, HID_, HID_, HID_, HID_, 0, 0, 0, 1.f, 1, 0);

    rms_kernel<<<S_, 256>>>(attnproj, hidden, w_post_attn, x, HID_);
    rms_kernel<<<S_, 256>>>(x, nullptr, w_pre_ff, h2, HID_);

    launch_gemm(h2, gate_up_w, gu, S_, 2 * INTER_, HID_, HID_, 2 * INTER_, 2 * INTER_, 0, 0, 0, 1.f, 1, 0);
    silu_mul_kernel<<<(S_ * INTER_) / 256, 256>>>(gu, act);

    launch_gemm(act, down_w, mlp, S_, HID_, INTER_, INTER_, HID_, HID_, 0, 0, 0, 1.f, 1, 0);

    rms_kernel<<<S_, 256>>>(mlp, x, w_post_ff, out, HID_);
}